// round 10
// baseline (speedup 1.0000x reference)
#include <cuda_runtime.h>
#include <cuda_bf16.h>
#include <math_constants.h>
#include <stdint.h>

#define KCODES 512
#define DDIM   64
#define NROW   65536
#define QELEMS 4194304
#define NBLK   148
#define NTHR   256
#define NTILES 1024            // 65536 / 64 rows per tile
#define TAU    1e-3f
#define CANDCAP 16

__device__ double   g_partial[NBLK];
__device__ unsigned g_count = 0;
__device__ __nv_bfloat16 g_wh[KCODES * DDIM];
__device__ __nv_bfloat16 g_wl[KCODES * DDIM];

// ---- smem layout (float offsets) ----
#define OFF_DT    0                    // [64][513] f32 distances
#define OFF_SX    32832                // [64][68] f32 exact x
#define OFF_SXH   37184                // [64][72] bf16 (as 2304 f)
#define OFF_SXL   39488                // [64][72] bf16
#define OFF_SA    41792                // [64] exact row norms
#define OFF_SB    41856                // [512] exact code norms
#define OFF_GMIN  42368                // [64]
#define OFF_CCNT  42432                // [64] int
#define OFF_CLIST 42496                // [64][16] int
#define OFF_WIN   43520                // [64] int
#define OFF_SRED  43584                // [256] double (43584*4 % 8 == 0)
#define SMEM_FLOATS (OFF_SRED + 512)
#define SMEM_BYTES  (SMEM_FLOATS * 4)  // 176384 B

// ---------------------------------------------------------------------------
// K1: split w into bf16 hi/lo planes (scratch in __device__ globals)
// ---------------------------------------------------------------------------
__global__ void prep_w(const float* __restrict__ w) {
    int k = blockIdx.x * blockDim.x + threadIdx.x;
    if (k < KCODES) {
        #pragma unroll
        for (int d = 0; d < DDIM; d++) {
            float v = w[k * DDIM + d];
            __nv_bfloat16 h = __float2bfloat16(v);
            g_wh[k * DDIM + d] = h;
            g_wl[k * DDIM + d] = __float2bfloat16(__fsub_rn(v, __bfloat162float(h)));
        }
    }
}

// ---------------------------------------------------------------------------
__device__ __forceinline__ void mma_bf16(float c[4], const unsigned a[4],
                                         const unsigned b[2]) {
    asm volatile(
        "mma.sync.aligned.m16n8k16.row.col.f32.bf16.bf16.f32 "
        "{%0,%1,%2,%3},{%4,%5,%6,%7},{%8,%9},{%0,%1,%2,%3};"
        : "+f"(c[0]), "+f"(c[1]), "+f"(c[2]), "+f"(c[3])
        : "r"(a[0]), "r"(a[1]), "r"(a[2]), "r"(a[3]), "r"(b[0]), "r"(b[1]));
}

// Zero enc rows; enc base only 4B-aligned -> scalar fringes + float4 interior
__device__ __forceinline__ void zero_rows(float* __restrict__ enc,
                                          int row0, int nrows, int tid) {
    float* p = enc + (size_t)row0 * KCODES;
    int n = nrows * KCODES;
    uintptr_t a = (uintptr_t)p;
    int head = (int)((((a + 15) & ~(uintptr_t)15) - a) >> 2);
    if (tid < head) p[tid] = 0.0f;
    int n4 = (n - head) >> 2;
    int tail = (n - head) & 3;
    float4* v = (float4*)(p + head);
    float4 z = make_float4(0.f, 0.f, 0.f, 0.f);
    for (int i = tid; i < n4; i += NTHR) v[i] = z;
    if (tid >= 4 && tid - 4 < tail) p[head + 4 * n4 + (tid - 4)] = 0.0f;
}

// ---------------------------------------------------------------------------
// K2: per 64-row tile: bf16-split MMA filter -> exact rescore -> outputs
// ---------------------------------------------------------------------------
__global__ void __launch_bounds__(NTHR, 1) vq_main(
    const float* __restrict__ x,
    const float* __restrict__ w,
    float* __restrict__ out,
    float* __restrict__ qout,
    float* __restrict__ enc)
{
    extern __shared__ float sm[];
    float* dt  = sm + OFF_DT;
    float* sx  = sm + OFF_SX;
    __nv_bfloat16* sxh = (__nv_bfloat16*)(sm + OFF_SXH);
    __nv_bfloat16* sxl = (__nv_bfloat16*)(sm + OFF_SXL);
    float* sa  = sm + OFF_SA;
    float* sb  = sm + OFF_SB;
    float* gmin = sm + OFF_GMIN;
    int*   ccnt = (int*)(sm + OFF_CCNT);
    int*   clist = (int*)(sm + OFF_CLIST);
    int*   win  = (int*)(sm + OFF_WIN);
    double* sred = (double*)(sm + OFF_SRED);

    const int tid  = threadIdx.x;
    const int bid  = blockIdx.x;
    const int wid  = tid >> 5;
    const int lane = tid & 31;

    // Tiles: blocks 0-135 get 7, 136-147 get 6  (136*7 + 12*6 = 1024)
    const int cnt   = (bid < 136) ? 7 : 6;
    const int t0    = (bid < 136) ? bid * 7 : 952 + (bid - 136) * 6;
    const int row0b = t0 * 64;

    // Zero-fill this block's enc rows (drains under compute)
    zero_rows(enc, row0b, cnt * 64, tid);

    // Exact code norms (reference rounding chain), once per block
    for (int k = tid; k < KCODES; k += NTHR) {
        float acc = 0.0f;
        #pragma unroll
        for (int d = 0; d < DDIM; d++) {
            float v = w[k * DDIM + d];
            acc = __fadd_rn(acc, __fmul_rn(v, v));
        }
        sb[k] = acc;
    }

    double ls = 0.0;

    for (int t = 0; t < cnt; t++) {
        const int row0 = (t0 + t) * 64;
        __syncthreads();   // dt/sx free from previous tile

        // ---- Stage x tile: fp32 + bf16 hi/lo split -----------------------
        // x [B=64,D=64,H=32,W=32]: row n -> (n>>10)*65536 + (n&1023) + d*1024
        #pragma unroll
        for (int i = 0; i < 16; i++) {
            int idx = i * NTHR + tid;          // 4096 items
            int r = idx & 63, d = idx >> 6;
            int n = row0 + r, b = n >> 10, hw = n & 1023;
            float v = x[(size_t)b * 65536 + hw + (size_t)d * 1024];
            sx[r * 68 + d] = v;
            __nv_bfloat16 h = __float2bfloat16(v);
            sxh[r * 72 + d] = h;
            sxl[r * 72 + d] = __float2bfloat16(__fsub_rn(v, __bfloat162float(h)));
        }
        __syncthreads();

        // Exact row norms (sequential chain)
        if (tid < 64) {
            const float* pr = sx + tid * 68;
            float acc = 0.0f;
            #pragma unroll
            for (int d = 0; d < DDIM; d++)
                acc = __fadd_rn(acc, __fmul_rn(pr[d], pr[d]));
            sa[tid] = acc;
        }
        __syncthreads();

        // ---- MMA filter: warp wid covers codes [wid*64, wid*64+64) ------
        for (int mt = 0; mt < 4; mt++) {
            // A fragments for 4 k-steps, hi+lo
            unsigned ah[4][4], al[4][4];
            {
                int r  = mt * 16 + (lane >> 2);
                int c  = (lane & 3) * 2;
                #pragma unroll
                for (int ks = 0; ks < 4; ks++) {
                    int kc = ks * 16 + c;
                    ah[ks][0] = *(const unsigned*)(sxh + r * 72 + kc);
                    ah[ks][1] = *(const unsigned*)(sxh + (r + 8) * 72 + kc);
                    ah[ks][2] = *(const unsigned*)(sxh + r * 72 + kc + 8);
                    ah[ks][3] = *(const unsigned*)(sxh + (r + 8) * 72 + kc + 8);
                    al[ks][0] = *(const unsigned*)(sxl + r * 72 + kc);
                    al[ks][1] = *(const unsigned*)(sxl + (r + 8) * 72 + kc);
                    al[ks][2] = *(const unsigned*)(sxl + r * 72 + kc + 8);
                    al[ks][3] = *(const unsigned*)(sxl + (r + 8) * 72 + kc + 8);
                }
            }
            for (int nt = 0; nt < 8; nt++) {
                const int cb = wid * 64 + nt * 8;
                // B fragments: n = cb + lane/4, k = ks*16 + (lane%4)*2 (+8)
                unsigned bh[4][2], bl[4][2];
                {
                    int n = cb + (lane >> 2);
                    int c = (lane & 3) * 2;
                    #pragma unroll
                    for (int ks = 0; ks < 4; ks++) {
                        int kc = ks * 16 + c;
                        bh[ks][0] = *(const unsigned*)(g_wh + n * DDIM + kc);
                        bh[ks][1] = *(const unsigned*)(g_wh + n * DDIM + kc + 8);
                        bl[ks][0] = *(const unsigned*)(g_wl + n * DDIM + kc);
                        bl[ks][1] = *(const unsigned*)(g_wl + n * DDIM + kc + 8);
                    }
                }
                float acc[4] = {0.f, 0.f, 0.f, 0.f};
                #pragma unroll
                for (int ks = 0; ks < 4; ks++) {
                    mma_bf16(acc, al[ks], bh[ks]);
                    mma_bf16(acc, ah[ks], bl[ks]);
                    mma_bf16(acc, ah[ks], bh[ks]);
                }
                // d~ = (a + b) - 2*m~  (filter only; any rounding ok)
                int rr = mt * 16 + (lane >> 2);
                int nn = cb + (lane & 3) * 2;
                dt[rr * 513 + nn]           = sa[rr] + sb[nn]     - 2.0f * acc[0];
                dt[rr * 513 + nn + 1]       = sa[rr] + sb[nn + 1] - 2.0f * acc[1];
                dt[(rr + 8) * 513 + nn]     = sa[rr + 8] + sb[nn]     - 2.0f * acc[2];
                dt[(rr + 8) * 513 + nn + 1] = sa[rr + 8] + sb[nn + 1] - 2.0f * acc[3];
            }
        }
        __syncthreads();

        // ---- Scan + candidates + exact rescore (1 thread per row) -------
        if (tid < 64) {
            const float* dr = dt + tid * 513;    // stride 513: conflict-free
            float mn = CUDART_INF_F;
            for (int k = 0; k < KCODES; k++) {
                float d = dr[k];
                if (d < mn) mn = d;
            }
            float thr = mn + TAU;
            int cc = 0;
            for (int k = 0; k < KCODES; k++) {
                if (dr[k] <= thr) {
                    if (cc < CANDCAP) clist[tid * CANDCAP + cc] = k;
                    cc++;
                }
            }
            // Exact rescore (reference rounding chain, first-index ties)
            const float* xr = sx + tid * 68;
            float a = sa[tid];
            float best = CUDART_INF_F; int bi = 0x7fffffff;
            int ncand = (cc <= CANDCAP) ? cc : KCODES;
            for (int ci = 0; ci < ncand; ci++) {
                int k = (cc <= CANDCAP) ? clist[tid * CANDCAP + ci] : ci;
                const float* wk = w + (size_t)k * DDIM;
                float m = 0.0f;
                #pragma unroll
                for (int d = 0; d < DDIM; d++)
                    m = __fmaf_rn(xr[d], wk[d], m);
                float dd = __fsub_rn(__fadd_rn(a, sb[k]), __fmul_rn(2.0f, m));
                if (dd < best || (dd == best && k < bi)) { best = dd; bi = k; }
            }
            win[tid] = bi;
        }
        __syncthreads();

        // ---- Epilogue: q_out (straight-through), one-hot, loss ----------
        #pragma unroll
        for (int i = 0; i < 16; i++) {
            int idx = i * NTHR + tid;
            int r = idx & 63, d = idx >> 6;
            int n = row0 + r, b = n >> 10, hw = n & 1023;
            int bi = win[r];
            float xv   = sx[r * 68 + d];
            float diff = __fsub_rn(w[(size_t)bi * DDIM + d], xv);
            qout[(size_t)b * 65536 + hw + (size_t)d * 1024] = __fadd_rn(xv, diff);
            ls += (double)__fmul_rn(diff, diff);
        }
        if (tid < 64)
            enc[(size_t)(row0 + tid) * KCODES + win[tid]] = 1.0f;
    }

    // ---- Deterministic loss reduction --------------------------------------
    __syncthreads();
    sred[tid] = ls;
    __syncthreads();
    for (int s = NTHR / 2; s > 0; s >>= 1) {
        if (tid < s) sred[tid] += sred[tid + s];
        __syncthreads();
    }
    __shared__ int isLast;
    if (tid == 0) {
        g_partial[bid] = sred[0];
        __threadfence();
        unsigned old = atomicAdd(&g_count, 1u);
        isLast = (old == NBLK - 1u) ? 1 : 0;
    }
    __syncthreads();
    if (isLast) {
        sred[tid] = (tid < NBLK) ? g_partial[tid] : 0.0;
        __syncthreads();
        for (int s = NTHR / 2; s > 0; s >>= 1) {
            if (tid < s) sred[tid] += sred[tid + s];
            __syncthreads();
        }
        if (tid == 0) {
            float m = (float)(sred[0] / (double)QELEMS);
            out[0] = __fadd_rn(m, __fmul_rn(0.25f, m));   // z_q + 0.25*z_e
            g_count = 0;                                  // reset for replay
        }
    }
}

// ---------------------------------------------------------------------------
extern "C" void kernel_launch(void* const* d_in, const int* in_sizes, int n_in,
                              void* d_out, int out_size) {
    const float* x = (const float*)d_in[0];   // [64,64,32,32] fp32
    const float* w = (const float*)d_in[1];   // [512,64] fp32
    float* out  = (float*)d_out;
    float* qout = out + 1;                    // [4194304] (4B-aligned only)
    float* enc  = out + 1 + QELEMS;           // [65536*512] (4B-aligned only)

    cudaFuncSetAttribute(vq_main, cudaFuncAttributeMaxDynamicSharedMemorySize,
                         SMEM_BYTES);

    prep_w<<<2, 256>>>(w);
    vq_main<<<NBLK, NTHR, SMEM_BYTES>>>(x, w, out, qout, enc);
}